// round 1
// baseline (speedup 1.0000x reference)
#include <cuda_runtime.h>
#include <math.h>

#define BSZ 8
#define LSEQ 4096
#define DM 512
#define NS 64
#define NROWS (BSZ*LSEQ)

// scratch (allocations forbidden -> device globals)
__device__ float g_Bu[NROWS*NS];
__device__ float g_states[NROWS*NS];
__device__ float g_At[NS*NS];
__device__ float g_A2t[NS*NS];
__device__ float g_A4t[NS*NS];

typedef unsigned long long u64;

__device__ __forceinline__ u64 splat2(float s) {
    u64 r; asm("mov.b64 %0, {%1, %1};" : "=l"(r) : "f"(s)); return r;
}
__device__ __forceinline__ u64 fma2(u64 a, u64 b, u64 c) {
    u64 d; asm("fma.rn.f32x2 %0, %1, %2, %3;" : "=l"(d) : "l"(a), "l"(b), "l"(c)); return d;
}
__device__ __forceinline__ void unpack2(u64 v, float& lo, float& hi) {
    asm("mov.b64 {%0, %1}, %2;" : "=f"(lo), "=f"(hi) : "l"(v));
}

// ---------------------------------------------------------------------------
// Kernel P: A2 = A@A, A4 = A2@A2, stored transposed (Mt[m][n] = M[n][m])
// ---------------------------------------------------------------------------
__global__ void prep_kernel(const float* __restrict__ A) {
    __shared__ float As[NS*NS];
    __shared__ float A2s[NS*NS];
    int tid = threadIdx.x;
    for (int i = tid; i < NS*NS; i += 256) As[i] = A[i];
    __syncthreads();
    for (int e = tid; e < NS*NS; e += 256) {
        int n = e >> 6, m = e & 63;
        float acc = 0.f;
        #pragma unroll 8
        for (int k = 0; k < NS; k++) acc += As[n*NS + k] * As[k*NS + m];
        A2s[e] = acc;
        g_A2t[m*NS + n] = acc;
        g_At[m*NS + n] = As[e];
    }
    __syncthreads();
    for (int e = tid; e < NS*NS; e += 256) {
        int n = e >> 6, m = e & 63;
        float acc = 0.f;
        #pragma unroll 8
        for (int k = 0; k < NS; k++) acc += A2s[n*NS + k] * A2s[k*NS + m];
        g_A4t[m*NS + n] = acc;
    }
}

// ---------------------------------------------------------------------------
// Kernel 1: Bu[row][n] = sum_k x[row][k] * B[n][k]
// block tile 128 rows x 64 cols, 128 threads, 8x8 micro-tile (f32x2 pairs on n)
// ---------------------------------------------------------------------------
#define K1_SMEM ((128*65 + 64*64)*4)
__global__ __launch_bounds__(128) void bu_kernel(const float* __restrict__ x,
                                                 const float* __restrict__ B) {
    extern __shared__ float sm[];
    float* xs = sm;               // [128][65] (odd stride -> conflict-free a-loads)
    float* bs = sm + 128*65;      // [64 k][64 n] transposed B chunk
    int tid = threadIdx.x;
    int tx = tid & 7, ty = tid >> 3;
    int row0 = blockIdx.x * 128;

    u64 acc[8][4];
    #pragma unroll
    for (int i = 0; i < 8; i++)
        #pragma unroll
        for (int p = 0; p < 4; p++) acc[i][p] = 0ull;

    for (int kc = 0; kc < 8; kc++) {
        int k0 = kc * 64;
        __syncthreads();
        // stage x tile: f: c4 = f&15 (lane-major -> coalesced global), r = f>>4
        #pragma unroll
        for (int it = 0; it < 16; it++) {
            int f = it*128 + tid;
            int c4 = (f & 15) * 4, r = f >> 4;
            float4 v = *reinterpret_cast<const float4*>(&x[(size_t)(row0 + r)*DM + k0 + c4]);
            xs[r*65 + c4 + 0] = v.x; xs[r*65 + c4 + 1] = v.y;
            xs[r*65 + c4 + 2] = v.z; xs[r*65 + c4 + 3] = v.w;
        }
        // stage B transposed: f: n = f&63 (lane-major -> conflict-free smem stores)
        #pragma unroll
        for (int it = 0; it < 8; it++) {
            int f = it*128 + tid;
            int n = f & 63, c4 = (f >> 6) * 4;
            float4 v = *reinterpret_cast<const float4*>(&B[(size_t)n*DM + k0 + c4]);
            bs[(c4 + 0)*64 + n] = v.x; bs[(c4 + 1)*64 + n] = v.y;
            bs[(c4 + 2)*64 + n] = v.z; bs[(c4 + 3)*64 + n] = v.w;
        }
        __syncthreads();
        #pragma unroll 2
        for (int k = 0; k < 64; k++) {
            float a[8];
            #pragma unroll
            for (int i = 0; i < 8; i++) a[i] = xs[(ty*8 + i)*65 + k];
            u64 bp[4];
            #pragma unroll
            for (int p = 0; p < 4; p++)
                bp[p] = *reinterpret_cast<const u64*>(&bs[k*64 + tx*8 + 2*p]);
            #pragma unroll
            for (int i = 0; i < 8; i++) {
                u64 as = splat2(a[i]);
                #pragma unroll
                for (int p = 0; p < 4; p++) acc[i][p] = fma2(as, bp[p], acc[i][p]);
            }
        }
    }
    #pragma unroll
    for (int i = 0; i < 8; i++) {
        size_t row = row0 + ty*8 + i;
        #pragma unroll
        for (int p = 0; p < 4; p++)
            *reinterpret_cast<u64*>(&g_Bu[row*NS + tx*8 + 2*p]) = acc[i][p];
    }
}

// ---------------------------------------------------------------------------
// Kernel 2: three parallel shift-passes  out_t = in_t + M * in_{t-delta}
// (delta = 1,2,4 with M = A, A^2, A^4)  == sum_{j=0..7} A^j Bu_{t-j}
// ---------------------------------------------------------------------------
#define T2 128
#define R2 136
#define K2_SMEM ((2*R2*64 + 3*4096)*4)

template<int DELTA>
__device__ __forceinline__ void do_pass(const float* __restrict__ in,
                                        float* __restrict__ out,
                                        const float* __restrict__ Mt,
                                        int warp, int lane) {
    for (int r0 = warp * 8; r0 < R2; r0 += 128) {
        u64 acc[8];
        #pragma unroll
        for (int j = 0; j < 8; j++)
            acc[j] = *reinterpret_cast<const u64*>(&in[(r0 + j)*64 + 2*lane]);
        for (int m = 0; m < 64; m++) {
            u64 mp = *reinterpret_cast<const u64*>(&Mt[m*64 + 2*lane]);
            #pragma unroll
            for (int j = 0; j < 8; j++) {
                int rs = r0 + j - DELTA;
                if (rs >= 0) acc[j] = fma2(mp, splat2(in[rs*64 + m]), acc[j]);
            }
        }
        #pragma unroll
        for (int j = 0; j < 8; j++)
            *reinterpret_cast<u64*>(&out[(r0 + j)*64 + 2*lane]) = acc[j];
    }
}

__global__ __launch_bounds__(512) void pass_kernel() {
    extern __shared__ float sm[];
    float* buf0 = sm;                 // [R2][64]
    float* buf1 = sm + R2*64;
    float* m1   = sm + 2*R2*64;       // At, A2t, A4t contiguous
    int tid = threadIdx.x;
    int warp = tid >> 5, lane = tid & 31;
    int b = blockIdx.x >> 5, c = blockIdx.x & 31;
    int t0 = c * T2;

    // stage Bu with 8-row halo (t<0 -> zeros == true zero initial state)
    for (int f4 = tid; f4 < R2*16; f4 += 512) {
        int r = f4 >> 4, n4 = (f4 & 15) * 4;
        int t = t0 - 8 + r;
        float4 v = make_float4(0.f, 0.f, 0.f, 0.f);
        if (t >= 0)
            v = *reinterpret_cast<const float4*>(&g_Bu[((size_t)b*LSEQ + t)*NS + n4]);
        *reinterpret_cast<float4*>(&buf0[r*64 + n4]) = v;
    }
    for (int f4 = tid; f4 < 3*1024; f4 += 512) {
        float4 v;
        if (f4 < 1024)      v = reinterpret_cast<const float4*>(g_At)[f4];
        else if (f4 < 2048) v = reinterpret_cast<const float4*>(g_A2t)[f4 - 1024];
        else                v = reinterpret_cast<const float4*>(g_A4t)[f4 - 2048];
        reinterpret_cast<float4*>(m1)[f4] = v;
    }
    __syncthreads();
    do_pass<1>(buf0, buf1, m1,          warp, lane);
    __syncthreads();
    do_pass<2>(buf1, buf0, m1 + 4096,   warp, lane);
    __syncthreads();
    do_pass<4>(buf0, buf1, m1 + 8192,   warp, lane);
    __syncthreads();
    for (int f4 = tid; f4 < T2*16; f4 += 512) {
        int r = f4 >> 4, n4 = (f4 & 15) * 4;
        *reinterpret_cast<float4*>(&g_states[((size_t)b*LSEQ + t0 + r)*NS + n4]) =
            *reinterpret_cast<const float4*>(&buf1[(r + 8)*64 + n4]);
    }
}

// ---------------------------------------------------------------------------
// Kernel 3: y = states @ C^T, exact-erf GELU, LayerNorm(512), write out
// 512 threads, 16 warps x 4 rows (rows share C^T loads), 64 rows/block
// ---------------------------------------------------------------------------
#define K3_SMEM ((64*512 + 64*64 + 1024)*4)
__global__ __launch_bounds__(512) void out_kernel(const float* __restrict__ C,
                                                  const float* __restrict__ gamma,
                                                  const float* __restrict__ beta,
                                                  float* __restrict__ out) {
    extern __shared__ float sm[];
    float* Ct = sm;                   // [64 n][512 d]  (Ct[n][d] = C[d][n])
    float* ss = sm + 64*512;          // [64 rows][64 n]
    float* gm = ss + 64*64;           // 512
    float* bt = gm + 512;
    int tid = threadIdx.x;
    int warp = tid >> 5, lane = tid & 31;
    int row0 = blockIdx.x * 64;

    // C transpose load: lanes over d -> conflict-free smem stores
    for (int f4 = tid; f4 < 8192; f4 += 512) {
        int d = f4 & 511, n4 = (f4 >> 9) * 4;
        float4 v = *reinterpret_cast<const float4*>(&C[(size_t)d*NS + n4]);
        Ct[(n4 + 0)*512 + d] = v.x; Ct[(n4 + 1)*512 + d] = v.y;
        Ct[(n4 + 2)*512 + d] = v.z; Ct[(n4 + 3)*512 + d] = v.w;
    }
    for (int f4 = tid; f4 < 1024; f4 += 512) {
        int r = f4 >> 4, n4 = (f4 & 15) * 4;
        *reinterpret_cast<float4*>(&ss[r*64 + n4]) =
            *reinterpret_cast<const float4*>(&g_states[((size_t)row0 + r)*NS + n4]);
    }
    if (tid < 512) { gm[tid] = gamma[tid]; bt[tid] = beta[tid]; }
    __syncthreads();

    u64 acc[4][8];
    #pragma unroll
    for (int j = 0; j < 4; j++)
        #pragma unroll
        for (int i = 0; i < 8; i++) acc[j][i] = 0ull;

    const float* srow = ss + warp*4*64;
    for (int n = 0; n < 64; n++) {
        u64 sp0 = splat2(srow[n]);
        u64 sp1 = splat2(srow[64 + n]);
        u64 sp2 = splat2(srow[128 + n]);
        u64 sp3 = splat2(srow[192 + n]);
        const float* crow = Ct + n*512 + 2*lane;
        #pragma unroll
        for (int i = 0; i < 8; i++) {
            u64 cp = *reinterpret_cast<const u64*>(&crow[i*64]);
            acc[0][i] = fma2(cp, sp0, acc[0][i]);
            acc[1][i] = fma2(cp, sp1, acc[1][i]);
            acc[2][i] = fma2(cp, sp2, acc[2][i]);
            acc[3][i] = fma2(cp, sp3, acc[3][i]);
        }
    }

    #pragma unroll
    for (int j = 0; j < 4; j++) {
        float y[16];
        float sum = 0.f, ssq = 0.f;
        #pragma unroll
        for (int i = 0; i < 8; i++) {
            float lo, hi; unpack2(acc[j][i], lo, hi);
            lo = 0.5f * lo * (1.0f + erff(lo * 0.70710678118654752440f));
            hi = 0.5f * hi * (1.0f + erff(hi * 0.70710678118654752440f));
            y[2*i] = lo; y[2*i + 1] = hi;
            sum += lo + hi; ssq += lo*lo + hi*hi;
        }
        #pragma unroll
        for (int off = 16; off > 0; off >>= 1) {
            sum += __shfl_xor_sync(0xffffffffu, sum, off);
            ssq += __shfl_xor_sync(0xffffffffu, ssq, off);
        }
        float mean = sum * (1.0f / 512.0f);
        float var  = ssq * (1.0f / 512.0f) - mean * mean;
        float rstd = rsqrtf(var + 1e-5f);
        size_t row = row0 + warp*4 + j;
        #pragma unroll
        for (int i = 0; i < 8; i++) {
            int d = i*64 + 2*lane;
            float2 o;
            o.x = (y[2*i]     - mean) * rstd * gm[d]     + bt[d];
            o.y = (y[2*i + 1] - mean) * rstd * gm[d + 1] + bt[d + 1];
            *reinterpret_cast<float2*>(&out[row*DM + d]) = o;
        }
    }
}

// ---------------------------------------------------------------------------
extern "C" void kernel_launch(void* const* d_in, const int* in_sizes, int n_in,
                              void* d_out, int out_size) {
    const float* x     = (const float*)d_in[0];
    const float* A     = (const float*)d_in[1];
    const float* B     = (const float*)d_in[2];
    const float* C     = (const float*)d_in[3];
    const float* gamma = (const float*)d_in[4];
    const float* beta  = (const float*)d_in[5];
    float* out = (float*)d_out;

    cudaFuncSetAttribute(bu_kernel,   cudaFuncAttributeMaxDynamicSharedMemorySize, K1_SMEM);
    cudaFuncSetAttribute(pass_kernel, cudaFuncAttributeMaxDynamicSharedMemorySize, K2_SMEM);
    cudaFuncSetAttribute(out_kernel,  cudaFuncAttributeMaxDynamicSharedMemorySize, K3_SMEM);

    prep_kernel<<<1, 256>>>(A);
    bu_kernel<<<NROWS/128, 128, K1_SMEM>>>(x, B);
    pass_kernel<<<BSZ * (LSEQ/T2), 512, K2_SMEM>>>();
    out_kernel<<<NROWS/64, 512, K3_SMEM>>>(C, gamma, beta, out);
}